// round 5
// baseline (speedup 1.0000x reference)
#include <cuda_runtime.h>
#include <cuda_bf16.h>
#include <cstdint>

// out[T,N] = (x[T,K] @ W[N,K]^T) * scales[N] + bias[N];  T=8192, N=4096, K=4096
//
// R4: int8 IMMA (mma.sync m16n8k32 s8) — tcgen05 unavailable (harness compiles
// plain compute_103). x quantized per-row into two s8 digits:
//   x = rowscale * (256*h + l) + err,  |err| <= 0.5*rowscale
// Both digit GEMMs accumulate exactly in s32; combined in fp32 epilogue.
// Pipeline: cp.async 4-stage, XOR-swizzled smem, ldmatrix, supertile raster.
// (R3 resubmit with signed-char fix.)

#define T_DIM 8192
#define N_DIM 4096
#define K_DIM 4096

#define BM 128
#define BN 128
#define BK 64
#define STAGES 4
#define THREADS 256
#define KITERS (K_DIM / BK)       // 64

// stage layout: A_hi 8KB | A_lo 8KB | B 8KB
#define AH_B 0
#define AL_B 8192
#define BB_B 16384
#define STAGE_B 24576
#define SMEM_TOTAL (STAGES * STAGE_B)   // 98304

// swizzle for 64B rows, conflict-free ldmatrix: XOR row bits 1-2 into chunk bits
#define SWZ(o) ((o) ^ (((o) >> 3) & 0x30))

// ---------------- scratch ----------------
__device__ __align__(16) signed char g_xh[(size_t)T_DIM * K_DIM];
__device__ __align__(16) signed char g_xl[(size_t)T_DIM * K_DIM];
__device__ __align__(16) signed char g_ws[(size_t)N_DIM * K_DIM];
__device__ float g_rs[T_DIM];

// ---------------- asm helpers ----------------
__device__ __forceinline__ uint32_t smem_u32(const void* p) {
    uint32_t a;
    asm("{ .reg .u64 t; cvta.to.shared.u64 t, %1; cvt.u32.u64 %0, t; }" : "=r"(a) : "l"(p));
    return a;
}
__device__ __forceinline__ void cp16(uint32_t dst, const void* src) {
    asm volatile("cp.async.cg.shared.global [%0], [%1], 16;" :: "r"(dst), "l"(src));
}
__device__ __forceinline__ void cp_commit() {
    asm volatile("cp.async.commit_group;" ::: "memory");
}
__device__ __forceinline__ void cp_wait3() {
    asm volatile("cp.async.wait_group 3;" ::: "memory");
}
__device__ __forceinline__ void cp_wait0() {
    asm volatile("cp.async.wait_group 0;" ::: "memory");
}
__device__ __forceinline__ void ldm4(uint32_t& r0, uint32_t& r1, uint32_t& r2, uint32_t& r3,
                                     uint32_t addr) {
    asm volatile("ldmatrix.sync.aligned.m8n8.x4.shared.b16 {%0,%1,%2,%3}, [%4];"
                 : "=r"(r0), "=r"(r1), "=r"(r2), "=r"(r3) : "r"(addr));
}
__device__ __forceinline__ void mma_s8(int* d, uint32_t a0, uint32_t a1, uint32_t a2,
                                       uint32_t a3, uint32_t b0, uint32_t b1) {
    asm volatile(
        "mma.sync.aligned.m16n8k32.row.col.s32.s8.s8.s32 "
        "{%0,%1,%2,%3}, {%4,%5,%6,%7}, {%8,%9}, {%0,%1,%2,%3};"
        : "+r"(d[0]), "+r"(d[1]), "+r"(d[2]), "+r"(d[3])
        : "r"(a0), "r"(a1), "r"(a2), "r"(a3), "r"(b0), "r"(b1));
}

// ---------------- prepass: per-row quantize x -> (h, l) s8 digits ----------------
__global__ void __launch_bounds__(256)
quantize_x_kernel(const float4* __restrict__ X4)
{
    const int row = blockIdx.x;
    const int tid = threadIdx.x;
    const int lane = tid & 31, wid = tid >> 5;

    float4 v[4];
    float mx = 0.0f;
    #pragma unroll
    for (int j = 0; j < 4; j++) {
        v[j] = X4[(size_t)row * 1024 + tid + j * 256];
        mx = fmaxf(mx, fmaxf(fmaxf(fabsf(v[j].x), fabsf(v[j].y)),
                             fmaxf(fabsf(v[j].z), fabsf(v[j].w))));
    }
    #pragma unroll
    for (int o = 16; o; o >>= 1)
        mx = fmaxf(mx, __shfl_xor_sync(0xFFFFFFFFu, mx, o));

    __shared__ float smax[8];
    if (lane == 0) smax[wid] = mx;
    __syncthreads();
    float bm = smax[0];
    #pragma unroll
    for (int i = 1; i < 8; i++) bm = fmaxf(bm, smax[i]);

    const float inv = (bm > 0.0f) ? (32512.0f / bm) : 0.0f;
    if (tid == 0) g_rs[row] = bm * (1.0f / 32512.0f);

    #pragma unroll
    for (int j = 0; j < 4; j++) {
        float e[4] = {v[j].x, v[j].y, v[j].z, v[j].w};
        char4 hc, lc;
        signed char* hp = &hc.x;
        signed char* lp = &lc.x;
        #pragma unroll
        for (int q = 0; q < 4; q++) {
            float vv = e[q] * inv;
            float hf = rintf(vv * (1.0f / 256.0f));
            float lf = rintf(vv) - 256.0f * hf;
            if (lf > 127.0f)       { hf += 1.0f; lf -= 256.0f; }
            else if (lf < -128.0f) { hf -= 1.0f; lf += 256.0f; }
            hp[q] = (signed char)hf;
            lp[q] = (signed char)lf;
        }
        size_t off = (size_t)row * K_DIM + (size_t)(tid + j * 256) * 4;
        *reinterpret_cast<char4*>(g_xh + off) = hc;
        *reinterpret_cast<char4*>(g_xl + off) = lc;
    }
}

__global__ void __launch_bounds__(256)
convert_w_kernel(const int4* __restrict__ W4, int n4)
{
    int i = blockIdx.x * blockDim.x + threadIdx.x;
    if (i >= n4) return;
    int4 v = W4[i];
    char4 c;
    c.x = (signed char)v.x; c.y = (signed char)v.y;
    c.z = (signed char)v.z; c.w = (signed char)v.w;
    *reinterpret_cast<char4*>(g_ws + (size_t)i * 4) = c;
}

// ---------------- main GEMM ----------------
__device__ __forceinline__ void fill_stage(uint32_t sb, int stage, int m0, int n0, int kk) {
    const int tid = threadIdx.x;
    const uint32_t base = sb + stage * STAGE_B;
    #pragma unroll
    for (int j = 0; j < 2; j++) {
        int i = tid + j * 256;
        int r = i >> 2, c = i & 3;
        uint32_t sw = SWZ((uint32_t)((r << 6) + (c << 4)));
        cp16(base + AH_B + sw, g_xh + (size_t)(m0 + r) * K_DIM + kk + c * 16);
        cp16(base + AL_B + sw, g_xl + (size_t)(m0 + r) * K_DIM + kk + c * 16);
        cp16(base + BB_B + sw, g_ws + (size_t)(n0 + r) * K_DIM + kk + c * 16);
    }
}

__global__ void __launch_bounds__(THREADS, 1)
qlinear_imma_kernel(const float* __restrict__ scales,
                    const float* __restrict__ bias,
                    float* __restrict__ Out)
{
    extern __shared__ char smem[];
    const uint32_t sb = smem_u32(smem);
    const int tid = threadIdx.x;
    const int wid = tid >> 5;
    const int lane = tid & 31;

    // supertile raster: 8 n-tiles per group for L2 reuse
    const int bid = blockIdx.x;
    const int g = bid >> 9;              // 512 = 8 * 64
    const int r = bid & 511;
    const int n0 = (g * 8 + (r & 7)) * BN;
    const int m0 = (r >> 3) * BM;

    // warp grid 4(M) x 2(N); warp tile 32M x 64N
    const int wm = wid >> 1;
    const int wn = wid & 1;
    const int mbase = wm * 32;
    const int nbase = wn * 64;

    int accH[2][8][4];
    int accL[2][8][4];
    #pragma unroll
    for (int mt = 0; mt < 2; mt++)
        #pragma unroll
        for (int nf = 0; nf < 8; nf++)
            #pragma unroll
            for (int q = 0; q < 4; q++) { accH[mt][nf][q] = 0; accL[mt][nf][q] = 0; }

    // prologue: fill stages 0..2
    #pragma unroll
    for (int s = 0; s < 3; s++) {
        fill_stage(sb, s, m0, n0, s * BK);
        cp_commit();
    }

    const int arow = lane & 15;
    const int achk = lane >> 4;

    for (int c = 0; c < KITERS; c++) {
        __syncthreads();                       // stage (c+3)&3 free to overwrite
        if (c + 3 < KITERS)
            fill_stage(sb, (c + 3) & 3, m0, n0, (c + 3) * BK);
        cp_commit();
        cp_wait3();                            // stage c&3 data arrived
        __syncthreads();

        const uint32_t base = sb + (c & 3) * STAGE_B;

        #pragma unroll
        for (int ks = 0; ks < 2; ks++) {
            const int chunk = ks * 2 + achk;

            // B fragments: 4 n16-tiles -> 8 n8 frags
            uint32_t bf[8][2];
            #pragma unroll
            for (int nt = 0; nt < 4; nt++) {
                int row = nbase + nt * 16 + arow;
                uint32_t addr = base + BB_B + SWZ((uint32_t)((row << 6) + (chunk << 4)));
                uint32_t r0, r1, r2, r3;
                ldm4(r0, r1, r2, r3, addr);
                bf[nt * 2 + 0][0] = r0; bf[nt * 2 + 0][1] = r2;
                bf[nt * 2 + 1][0] = r1; bf[nt * 2 + 1][1] = r3;
            }

            #pragma unroll
            for (int mt = 0; mt < 2; mt++) {
                int row = mbase + mt * 16 + arow;
                uint32_t sw = SWZ((uint32_t)((row << 6) + (chunk << 4)));
                uint32_t a0, a1, a2, a3;
                ldm4(a0, a1, a2, a3, base + AH_B + sw);
                #pragma unroll
                for (int nf = 0; nf < 8; nf++)
                    mma_s8(accH[mt][nf], a0, a1, a2, a3, bf[nf][0], bf[nf][1]);
                ldm4(a0, a1, a2, a3, base + AL_B + sw);
                #pragma unroll
                for (int nf = 0; nf < 8; nf++)
                    mma_s8(accL[mt][nf], a0, a1, a2, a3, bf[nf][0], bf[nf][1]);
            }
        }
    }
    cp_wait0();

    // ---- epilogue: combine digits, scale+bias, direct float2 stores ----
    #pragma unroll
    for (int mt = 0; mt < 2; mt++) {
        const int mrow = m0 + mbase + mt * 16 + (lane >> 2);
        const float rsA = g_rs[mrow];
        const float rsB = g_rs[mrow + 8];
        #pragma unroll
        for (int nf = 0; nf < 8; nf++) {
            const int n = n0 + nbase + nf * 8 + (lane & 3) * 2;
            float2 sc = *reinterpret_cast<const float2*>(scales + n);
            float2 bi = *reinterpret_cast<const float2*>(bias + n);
            float2 o0, o1;
            o0.x = rsA * (256.0f * (float)accH[mt][nf][0] + (float)accL[mt][nf][0]) * sc.x + bi.x;
            o0.y = rsA * (256.0f * (float)accH[mt][nf][1] + (float)accL[mt][nf][1]) * sc.y + bi.y;
            o1.x = rsB * (256.0f * (float)accH[mt][nf][2] + (float)accL[mt][nf][2]) * sc.x + bi.x;
            o1.y = rsB * (256.0f * (float)accH[mt][nf][3] + (float)accL[mt][nf][3]) * sc.y + bi.y;
            *reinterpret_cast<float2*>(Out + (size_t)mrow * N_DIM + n) = o0;
            *reinterpret_cast<float2*>(Out + (size_t)(mrow + 8) * N_DIM + n) = o1;
        }
    }
}

// ---------------- host ----------------
extern "C" void kernel_launch(void* const* d_in, const int* in_sizes, int n_in,
                              void* d_out, int out_size)
{
    const float* x      = (const float*)d_in[0];
    const int*   w      = (const int*)d_in[1];
    const float* scales = (const float*)d_in[2];
    const float* bias   = (const float*)d_in[3];
    float* out = (float*)d_out;

    cudaFuncSetAttribute(qlinear_imma_kernel,
                         cudaFuncAttributeMaxDynamicSharedMemorySize, SMEM_TOTAL);

    quantize_x_kernel<<<T_DIM, 256>>>((const float4*)x);
    {
        int n4 = N_DIM * K_DIM / 4;
        convert_w_kernel<<<(n4 + 255) / 256, 256>>>((const int4*)w, n4);
    }

    qlinear_imma_kernel<<<(T_DIM / BM) * (N_DIM / BN), THREADS, SMEM_TOTAL>>>(scales, bias, out);
}

// round 6
// speedup vs baseline: 4.5419x; 4.5419x over previous
#include <cuda_runtime.h>
#include <cuda_fp16.h>
#include <cstdint>

// out[T,N] = (x[T,K] @ W[N,K]^T) * scales[N] + bias[N];  T=8192, N=4096, K=4096
//
// R5: single-digit fp16 HMMA (mma.sync m16n8k16.f32.f16.f16.f32).
//  - W int8-valued -> exact in fp16. x -> fp16 RN (rel err ~2.8e-4 << 1e-3).
//  - Legacy IMMA measured ~3x slower per instr on sm_103 (R4) -> fp16 HMMA.
//  - CTA tile 128(M) x 256(N), BK=64, 3-stage cp.async, SW128 swizzle,
//    8 warps (2M x 4N), warp tile 64x64, ldmatrix fragments.

#define T_DIM 8192
#define N_DIM 4096
#define K_DIM 4096

#define BM 128
#define BN 256
#define BK 64
#define STAGES 3
#define THREADS 256
#define KITERS (K_DIM / BK)      // 64

// stage layout: A 16KB | B 32KB
#define A_B 0
#define B_B 16384
#define STAGE_B 49152
#define SMEM_TOTAL (STAGES * STAGE_B)   // 147456

// SW128 swizzle for 128-byte rows (8 x 16B chunks): conflict-free ldmatrix
#define SWZ(o) ((o) ^ (((o) >> 3) & 0x70))

// ---------------- scratch ----------------
__device__ __align__(16) __half g_x[(size_t)T_DIM * K_DIM];   // 64 MB
__device__ __align__(16) __half g_w[(size_t)N_DIM * K_DIM];   // 32 MB

// ---------------- asm helpers ----------------
__device__ __forceinline__ uint32_t smem_u32(const void* p) {
    uint32_t a;
    asm("{ .reg .u64 t; cvta.to.shared.u64 t, %1; cvt.u32.u64 %0, t; }" : "=r"(a) : "l"(p));
    return a;
}
__device__ __forceinline__ void cp16(uint32_t dst, const void* src) {
    asm volatile("cp.async.cg.shared.global [%0], [%1], 16;" :: "r"(dst), "l"(src));
}
__device__ __forceinline__ void cp_commit() {
    asm volatile("cp.async.commit_group;" ::: "memory");
}
__device__ __forceinline__ void cp_wait2() {
    asm volatile("cp.async.wait_group 2;" ::: "memory");
}
__device__ __forceinline__ void cp_wait0() {
    asm volatile("cp.async.wait_group 0;" ::: "memory");
}
__device__ __forceinline__ void ldm4(uint32_t& r0, uint32_t& r1, uint32_t& r2, uint32_t& r3,
                                     uint32_t addr) {
    asm volatile("ldmatrix.sync.aligned.m8n8.x4.shared.b16 {%0,%1,%2,%3}, [%4];"
                 : "=r"(r0), "=r"(r1), "=r"(r2), "=r"(r3) : "r"(addr));
}
__device__ __forceinline__ void mma_f16(float* d, uint32_t a0, uint32_t a1, uint32_t a2,
                                        uint32_t a3, uint32_t b0, uint32_t b1) {
    asm volatile(
        "mma.sync.aligned.m16n8k16.row.col.f32.f16.f16.f32 "
        "{%0,%1,%2,%3}, {%4,%5,%6,%7}, {%8,%9}, {%0,%1,%2,%3};"
        : "+f"(d[0]), "+f"(d[1]), "+f"(d[2]), "+f"(d[3])
        : "r"(a0), "r"(a1), "r"(a2), "r"(a3), "r"(b0), "r"(b1));
}

// ---------------- prepass ----------------
__global__ void __launch_bounds__(256)
convert_x_kernel(const float4* __restrict__ X4, int n4)
{
    int i = blockIdx.x * blockDim.x + threadIdx.x;
    if (i >= n4) return;
    float4 v = X4[i];
    __half2 h0 = __floats2half2_rn(v.x, v.y);
    __half2 h1 = __floats2half2_rn(v.z, v.w);
    uint2 u;
    u.x = *reinterpret_cast<uint32_t*>(&h0);
    u.y = *reinterpret_cast<uint32_t*>(&h1);
    *reinterpret_cast<uint2*>(g_x + (size_t)i * 4) = u;
}

__global__ void __launch_bounds__(256)
convert_w_kernel(const int4* __restrict__ W4, int n4)
{
    int i = blockIdx.x * blockDim.x + threadIdx.x;
    if (i >= n4) return;
    int4 v = W4[i];
    __half2 h0 = __floats2half2_rn((float)v.x, (float)v.y);
    __half2 h1 = __floats2half2_rn((float)v.z, (float)v.w);
    uint2 u;
    u.x = *reinterpret_cast<uint32_t*>(&h0);
    u.y = *reinterpret_cast<uint32_t*>(&h1);
    *reinterpret_cast<uint2*>(g_w + (size_t)i * 4) = u;
}

// ---------------- main GEMM ----------------
__device__ __forceinline__ void fill_stage(uint32_t sb, int stage, int m0, int n0, int kk) {
    const int tid = threadIdx.x;
    const uint32_t base = sb + stage * STAGE_B;
    #pragma unroll
    for (int j = 0; j < 4; j++) {               // A: 128 rows x 8 chunks
        int i = tid + j * 256;
        int r = i >> 3, c = i & 7;
        cp16(base + A_B + SWZ((uint32_t)((r << 7) + (c << 4))),
             g_x + (size_t)(m0 + r) * K_DIM + kk + c * 8);
    }
    #pragma unroll
    for (int j = 0; j < 8; j++) {               // B: 256 rows x 8 chunks
        int i = tid + j * 256;
        int r = i >> 3, c = i & 7;
        cp16(base + B_B + SWZ((uint32_t)((r << 7) + (c << 4))),
             g_w + (size_t)(n0 + r) * K_DIM + kk + c * 8);
    }
}

__global__ void __launch_bounds__(THREADS, 1)
qlinear_hmma_kernel(const float* __restrict__ scales,
                    const float* __restrict__ bias,
                    float* __restrict__ Out)
{
    extern __shared__ char smem[];
    const uint32_t sb = smem_u32(smem);
    const int tid = threadIdx.x;
    const int wid = tid >> 5;
    const int lane = tid & 31;

    const int n0 = blockIdx.x * BN;
    const int m0 = blockIdx.y * BM;

    // warp grid: 2(M) x 4(N); warp tile 64x64
    const int wm = wid & 1;
    const int wn = wid >> 1;

    float acc[4][8][4];
    #pragma unroll
    for (int mt = 0; mt < 4; mt++)
        #pragma unroll
        for (int nf = 0; nf < 8; nf++)
            #pragma unroll
            for (int q = 0; q < 4; q++) acc[mt][nf][q] = 0.0f;

    // prologue: stages 0,1
    fill_stage(sb, 0, m0, n0, 0);
    cp_commit();
    fill_stage(sb, 1, m0, n0, BK);
    cp_commit();

    const int frow = lane & 15;      // fragment row (m or n)
    const int fcol = lane >> 4;      // 16B k-half within k16

    for (int c = 0; c < KITERS; c++) {
        __syncthreads();                       // prior consumers of refill slot done
        if (c + 2 < KITERS)
            fill_stage(sb, (c + 2) % STAGES, m0, n0, (c + 2) * BK);
        cp_commit();
        cp_wait2();                            // stage c's group complete
        __syncthreads();

        const uint32_t base = sb + (c % STAGES) * STAGE_B;

        #pragma unroll
        for (int ks = 0; ks < 4; ks++) {
            // B fragments: 4 ldmatrix.x4 -> 8 n8 frags
            uint32_t bf[8][2];
            #pragma unroll
            for (int nt = 0; nt < 4; nt++) {
                int row = wn * 64 + nt * 16 + frow;
                uint32_t addr = base + B_B +
                    SWZ((uint32_t)((row << 7) + ks * 32 + (fcol << 4)));
                uint32_t r0, r1, r2, r3;
                ldm4(r0, r1, r2, r3, addr);
                bf[nt * 2 + 0][0] = r0; bf[nt * 2 + 0][1] = r2;
                bf[nt * 2 + 1][0] = r1; bf[nt * 2 + 1][1] = r3;
            }
            // A fragments + MMAs
            #pragma unroll
            for (int mt = 0; mt < 4; mt++) {
                int row = wm * 64 + mt * 16 + frow;
                uint32_t addr = base + A_B +
                    SWZ((uint32_t)((row << 7) + ks * 32 + (fcol << 4)));
                uint32_t a0, a1, a2, a3;
                ldm4(a0, a1, a2, a3, addr);
                #pragma unroll
                for (int nf = 0; nf < 8; nf++)
                    mma_f16(acc[mt][nf], a0, a1, a2, a3, bf[nf][0], bf[nf][1]);
            }
        }
    }
    cp_wait0();

    // ---- epilogue: scale + bias, direct float2 stores ----
    #pragma unroll
    for (int mt = 0; mt < 4; mt++) {
        const int mrow = m0 + wm * 64 + mt * 16 + (lane >> 2);
        #pragma unroll
        for (int nf = 0; nf < 8; nf++) {
            const int n = n0 + wn * 64 + nf * 8 + (lane & 3) * 2;
            float2 sc = *reinterpret_cast<const float2*>(scales + n);
            float2 bi = *reinterpret_cast<const float2*>(bias + n);
            float2 o0, o1;
            o0.x = acc[mt][nf][0] * sc.x + bi.x;
            o0.y = acc[mt][nf][1] * sc.y + bi.y;
            o1.x = acc[mt][nf][2] * sc.x + bi.x;
            o1.y = acc[mt][nf][3] * sc.y + bi.y;
            *reinterpret_cast<float2*>(Out + (size_t)mrow * N_DIM + n) = o0;
            *reinterpret_cast<float2*>(Out + (size_t)(mrow + 8) * N_DIM + n) = o1;
        }
    }
}

// ---------------- host ----------------
extern "C" void kernel_launch(void* const* d_in, const int* in_sizes, int n_in,
                              void* d_out, int out_size)
{
    const float* x      = (const float*)d_in[0];
    const int*   w      = (const int*)d_in[1];
    const float* scales = (const float*)d_in[2];
    const float* bias   = (const float*)d_in[3];
    float* out = (float*)d_out;

    cudaFuncSetAttribute(qlinear_hmma_kernel,
                         cudaFuncAttributeMaxDynamicSharedMemorySize, SMEM_TOTAL);

    {
        int n4 = T_DIM * K_DIM / 4;
        convert_x_kernel<<<(n4 + 255) / 256, 256>>>((const float4*)x, n4);
    }
    {
        int n4 = N_DIM * K_DIM / 4;
        convert_w_kernel<<<(n4 + 255) / 256, 256>>>((const int4*)w, n4);
    }

    dim3 grid(N_DIM / BN, T_DIM / BM);   // 16 x 64
    qlinear_hmma_kernel<<<grid, THREADS, SMEM_TOTAL>>>(scales, bias, out);
}

// round 7
// speedup vs baseline: 4.9311x; 1.0857x over previous
#include <cuda_runtime.h>
#include <cuda_fp16.h>
#include <cstdint>

// out[T,N] = (x[T,K] @ W[N,K]^T) * scales[N] + bias[N];  T=8192, N=4096, K=4096
//
// R6: fp16 HMMA, same tiles as R5 (CTA 128x256, BK=64, warp 64x64, 3-stage
// cp.async) with pipeline restructured for overlap:
//   - ONE __syncthreads per k-iter (wait -> sync -> fill next -> compute)
//   - fill issued before compute so LDG latency hides behind MMAs
//   - ldmatrix swizzled addresses hoisted (XOR-composable swizzle)

#define T_DIM 8192
#define N_DIM 4096
#define K_DIM 4096

#define BM 128
#define BN 256
#define BK 64
#define STAGES 3
#define THREADS 256
#define KITERS (K_DIM / BK)      // 64

#define A_B 0
#define B_B 16384
#define STAGE_B 49152
#define SMEM_TOTAL (STAGES * STAGE_B)   // 147456

#define SWZ(o) ((o) ^ (((o) >> 3) & 0x70))

__device__ __align__(16) __half g_x[(size_t)T_DIM * K_DIM];
__device__ __align__(16) __half g_w[(size_t)N_DIM * K_DIM];

// ---------------- asm helpers ----------------
__device__ __forceinline__ uint32_t smem_u32(const void* p) {
    uint32_t a;
    asm("{ .reg .u64 t; cvta.to.shared.u64 t, %1; cvt.u32.u64 %0, t; }" : "=r"(a) : "l"(p));
    return a;
}
__device__ __forceinline__ void cp16(uint32_t dst, const void* src) {
    asm volatile("cp.async.cg.shared.global [%0], [%1], 16;" :: "r"(dst), "l"(src));
}
__device__ __forceinline__ void cp_commit() {
    asm volatile("cp.async.commit_group;" ::: "memory");
}
__device__ __forceinline__ void cp_wait1() {
    asm volatile("cp.async.wait_group 1;" ::: "memory");
}
__device__ __forceinline__ void cp_wait0() {
    asm volatile("cp.async.wait_group 0;" ::: "memory");
}
__device__ __forceinline__ void ldm4(uint32_t& r0, uint32_t& r1, uint32_t& r2, uint32_t& r3,
                                     uint32_t addr) {
    asm volatile("ldmatrix.sync.aligned.m8n8.x4.shared.b16 {%0,%1,%2,%3}, [%4];"
                 : "=r"(r0), "=r"(r1), "=r"(r2), "=r"(r3) : "r"(addr));
}
__device__ __forceinline__ void mma_f16(float* d, uint32_t a0, uint32_t a1, uint32_t a2,
                                        uint32_t a3, uint32_t b0, uint32_t b1) {
    asm volatile(
        "mma.sync.aligned.m16n8k16.row.col.f32.f16.f16.f32 "
        "{%0,%1,%2,%3}, {%4,%5,%6,%7}, {%8,%9}, {%0,%1,%2,%3};"
        : "+f"(d[0]), "+f"(d[1]), "+f"(d[2]), "+f"(d[3])
        : "r"(a0), "r"(a1), "r"(a2), "r"(a3), "r"(b0), "r"(b1));
}

// ---------------- prepass ----------------
__global__ void __launch_bounds__(256)
convert_x_kernel(const float4* __restrict__ X4, int n4)
{
    int i = blockIdx.x * blockDim.x + threadIdx.x;
    if (i >= n4) return;
    float4 v = X4[i];
    __half2 h0 = __floats2half2_rn(v.x, v.y);
    __half2 h1 = __floats2half2_rn(v.z, v.w);
    uint2 u;
    u.x = *reinterpret_cast<uint32_t*>(&h0);
    u.y = *reinterpret_cast<uint32_t*>(&h1);
    *reinterpret_cast<uint2*>(g_x + (size_t)i * 4) = u;
}

__global__ void __launch_bounds__(256)
convert_w_kernel(const int4* __restrict__ W4, int n4)
{
    int i = blockIdx.x * blockDim.x + threadIdx.x;
    if (i >= n4) return;
    int4 v = W4[i];
    __half2 h0 = __floats2half2_rn((float)v.x, (float)v.y);
    __half2 h1 = __floats2half2_rn((float)v.z, (float)v.w);
    uint2 u;
    u.x = *reinterpret_cast<uint32_t*>(&h0);
    u.y = *reinterpret_cast<uint32_t*>(&h1);
    *reinterpret_cast<uint2*>(g_w + (size_t)i * 4) = u;
}

// ---------------- main GEMM ----------------
__device__ __forceinline__ void fill_stage(uint32_t base, int m0, int n0, int kk,
                                           int tid) {
    #pragma unroll
    for (int j = 0; j < 4; j++) {               // A: 128 rows x 8 chunks
        int i = tid + j * 256;
        int r = i >> 3, c = i & 7;
        cp16(base + A_B + SWZ((uint32_t)((r << 7) + (c << 4))),
             g_x + (size_t)(m0 + r) * K_DIM + kk + c * 8);
    }
    #pragma unroll
    for (int j = 0; j < 8; j++) {               // B: 256 rows x 8 chunks
        int i = tid + j * 256;
        int r = i >> 3, c = i & 7;
        cp16(base + B_B + SWZ((uint32_t)((r << 7) + (c << 4))),
             g_w + (size_t)(n0 + r) * K_DIM + kk + c * 8);
    }
}

__global__ void __launch_bounds__(THREADS, 1)
qlinear_hmma_kernel(const float* __restrict__ scales,
                    const float* __restrict__ bias,
                    float* __restrict__ Out)
{
    extern __shared__ char smem[];
    const uint32_t sb = smem_u32(smem);
    const int tid = threadIdx.x;
    const int wid = tid >> 5;
    const int lane = tid & 31;

    const int n0 = blockIdx.x * BN;
    const int m0 = blockIdx.y * BM;

    const int wm = wid & 1;        // 2 warps over M
    const int wn = wid >> 1;       // 4 warps over N

    // precomputed swizzled ldmatrix bases (stage-relative); kpart XORs in
    const int frow = lane & 15;
    const int fcol = lane >> 4;
    uint32_t aoff[4], boff[4];
    #pragma unroll
    for (int mt = 0; mt < 4; mt++) {
        uint32_t row = (uint32_t)(wm * 64 + mt * 16 + frow);
        aoff[mt] = A_B + ((row << 7) ^ ((row & 7) << 4)) + 0;  // kpart XORed later
    }
    #pragma unroll
    for (int nt = 0; nt < 4; nt++) {
        uint32_t row = (uint32_t)(wn * 64 + nt * 16 + frow);
        boff[nt] = B_B + ((row << 7) ^ ((row & 7) << 4));
    }
    const uint32_t kbase = (uint32_t)(fcol << 4);   // 0 or 16

    float acc[4][8][4];
    #pragma unroll
    for (int mt = 0; mt < 4; mt++)
        #pragma unroll
        for (int nf = 0; nf < 8; nf++)
            #pragma unroll
            for (int q = 0; q < 4; q++) acc[mt][nf][q] = 0.0f;

    // prologue: stages 0,1
    fill_stage(sb + 0 * STAGE_B, m0, n0, 0, tid);
    cp_commit();
    fill_stage(sb + 1 * STAGE_B, m0, n0, BK, tid);
    cp_commit();

    int cons = 0;                 // stage being consumed
    int prod = 2;                 // stage being produced
    for (int c = 0; c < KITERS; c++) {
        cp_wait1();               // stage `cons` data arrived
        __syncthreads();          // everyone done with stage `prod` (iter c-1)

        if (c + 2 < KITERS)
            fill_stage(sb + prod * STAGE_B, m0, n0, (c + 2) * BK, tid);
        cp_commit();

        const uint32_t base = sb + cons * STAGE_B;

        #pragma unroll
        for (int ks = 0; ks < 4; ks++) {
            const uint32_t kpart = kbase + (uint32_t)(ks * 32);

            uint32_t bf[8][2];
            #pragma unroll
            for (int nt = 0; nt < 4; nt++) {
                uint32_t r0, r1, r2, r3;
                ldm4(r0, r1, r2, r3, base + (boff[nt] ^ kpart));
                bf[nt * 2 + 0][0] = r0; bf[nt * 2 + 0][1] = r2;
                bf[nt * 2 + 1][0] = r1; bf[nt * 2 + 1][1] = r3;
            }
            #pragma unroll
            for (int mt = 0; mt < 4; mt++) {
                uint32_t a0, a1, a2, a3;
                ldm4(a0, a1, a2, a3, base + (aoff[mt] ^ kpart));
                #pragma unroll
                for (int nf = 0; nf < 8; nf++)
                    mma_f16(acc[mt][nf], a0, a1, a2, a3, bf[nf][0], bf[nf][1]);
            }
        }

        cons = (cons == STAGES - 1) ? 0 : cons + 1;
        prod = (prod == STAGES - 1) ? 0 : prod + 1;
    }
    cp_wait0();

    // ---- epilogue ----
    #pragma unroll
    for (int mt = 0; mt < 4; mt++) {
        const int mrow = m0 + wm * 64 + mt * 16 + (lane >> 2);
        #pragma unroll
        for (int nf = 0; nf < 8; nf++) {
            const int n = n0 + wn * 64 + nf * 8 + (lane & 3) * 2;
            float2 sc = *reinterpret_cast<const float2*>(scales + n);
            float2 bi = *reinterpret_cast<const float2*>(bias + n);
            float2 o0, o1;
            o0.x = acc[mt][nf][0] * sc.x + bi.x;
            o0.y = acc[mt][nf][1] * sc.y + bi.y;
            o1.x = acc[mt][nf][2] * sc.x + bi.x;
            o1.y = acc[mt][nf][3] * sc.y + bi.y;
            *reinterpret_cast<float2*>(Out + (size_t)mrow * N_DIM + n) = o0;
            *reinterpret_cast<float2*>(Out + (size_t)(mrow + 8) * N_DIM + n) = o1;
        }
    }
}

// ---------------- host ----------------
extern "C" void kernel_launch(void* const* d_in, const int* in_sizes, int n_in,
                              void* d_out, int out_size)
{
    const float* x      = (const float*)d_in[0];
    const int*   w      = (const int*)d_in[1];
    const float* scales = (const float*)d_in[2];
    const float* bias   = (const float*)d_in[3];
    float* out = (float*)d_out;

    cudaFuncSetAttribute(qlinear_hmma_kernel,
                         cudaFuncAttributeMaxDynamicSharedMemorySize, SMEM_TOTAL);

    {
        int n4 = T_DIM * K_DIM / 4;
        convert_x_kernel<<<(n4 + 255) / 256, 256>>>((const float4*)x, n4);
    }
    {
        int n4 = N_DIM * K_DIM / 4;
        convert_w_kernel<<<(n4 + 255) / 256, 256>>>((const int4*)w, n4);
    }

    dim3 grid(N_DIM / BN, T_DIM / BM);   // 16 x 64
    qlinear_hmma_kernel<<<grid, THREADS, SMEM_TOTAL>>>(scales, bias, out);
}